// round 4
// baseline (speedup 1.0000x reference)
#include <cuda_runtime.h>
#include <math.h>
#include <stdint.h>

#define B_ 8
#define C_ 64
#define N_ 4096

// support[b][j][c] = (X^T W)  row-major in (j, c)
__device__ float g_support[B_ * N_ * C_];
__device__ float g_norms2[B_ * N_];
__device__ float g_R2[B_];

// ---------------- helpers ----------------
__device__ __forceinline__ uint32_t f2tf32(float x) {
    uint32_t u;
    asm("cvt.rna.tf32.f32 %0, %1;" : "=r"(u) : "f"(x));
    return u;
}
__device__ __forceinline__ float ex2f(float x) {
    float y;
    asm("ex2.approx.f32 %0, %1;" : "=f"(y) : "f"(x));
    return y;
}
__device__ __forceinline__ void mma_tf32(float* d, const uint32_t* a, const uint32_t* b) {
    asm volatile(
        "mma.sync.aligned.m16n8k8.row.col.f32.tf32.tf32.f32 "
        "{%0,%1,%2,%3}, {%4,%5,%6,%7}, {%8,%9}, {%0,%1,%2,%3};"
        : "+f"(d[0]), "+f"(d[1]), "+f"(d[2]), "+f"(d[3])
        : "r"(a[0]), "r"(a[1]), "r"(a[2]), "r"(a[3]), "r"(b[0]), "r"(b[1]));
}
__device__ __forceinline__ void cpa16(uint32_t dst, const void* src) {
    asm volatile("cp.async.cg.shared.global [%0], [%1], 16;" :: "r"(dst), "l"(src));
}
#define CP_COMMIT() asm volatile("cp.async.commit_group;" ::: "memory")
#define CP_WAIT(n)  asm volatile("cp.async.wait_group %0;" :: "n"(n) : "memory")

// ---------------- prep kernels ----------------
__global__ void init_kernel() {
    if (threadIdx.x < B_) g_R2[threadIdx.x] = 0.f;
}

__global__ __launch_bounds__(256) void norms_kernel(const float* __restrict__ x) {
    int b = blockIdx.y;
    int i = blockIdx.x * 256 + threadIdx.x;
    const float* xb = x + (size_t)b * C_ * N_;
    float s = 0.f;
#pragma unroll 8
    for (int c = 0; c < C_; c++) {
        float v = xb[(size_t)c * N_ + i];
        s = fmaf(v, v, s);
    }
    g_norms2[b * N_ + i] = s;
    float m = s;
#pragma unroll
    for (int off = 16; off > 0; off >>= 1)
        m = fmaxf(m, __shfl_xor_sync(0xffffffffu, m, off));
    __shared__ float wm[8];
    if ((threadIdx.x & 31) == 0) wm[threadIdx.x >> 5] = m;
    __syncthreads();
    if (threadIdx.x == 0) {
        float bm = wm[0];
#pragma unroll
        for (int k = 1; k < 8; k++) bm = fmaxf(bm, wm[k]);
        atomicMax((int*)&g_R2[b], __float_as_int(bm));  // positive floats: int-max valid
    }
}

// support[b, j, c] = sum_k x[b, k, j] * w[k, c]   (exact fp32)
__global__ __launch_bounds__(256) void support_kernel(const float* __restrict__ x,
                                                      const float* __restrict__ w) {
    __shared__ float ws[64 * 64];
    __shared__ float xs[64 * 64];
    const int b  = blockIdx.y;
    const int jb = blockIdx.x * 64;
    const int t  = threadIdx.x;
    const int tx = t & 15, ty = t >> 4;
    const float* xb = x + (size_t)b * C_ * N_;

    for (int idx = t; idx < 1024; idx += 256) {
        ((float4*)ws)[idx] = ((const float4*)w)[idx];
        int k = idx >> 4, f = idx & 15;
        ((float4*)xs)[idx] = *(const float4*)(xb + k * N_ + jb + 4 * f);
    }
    __syncthreads();

    float acc[4][4] = {};
#pragma unroll 8
    for (int k = 0; k < 64; k++) {
        float4 xv = *(float4*)(xs + k * 64 + 4 * ty);
        float4 wv = *(float4*)(ws + k * 64 + 4 * tx);
        float xa[4] = {xv.x, xv.y, xv.z, xv.w};
        float wa[4] = {wv.x, wv.y, wv.z, wv.w};
#pragma unroll
        for (int jj = 0; jj < 4; jj++)
#pragma unroll
            for (int cc = 0; cc < 4; cc++)
                acc[jj][cc] = fmaf(xa[jj], wa[cc], acc[jj][cc]);
    }
    float* sb = g_support + ((size_t)b * N_ + jb) * C_;
#pragma unroll
    for (int jj = 0; jj < 4; jj++) {
        float4 r = make_float4(acc[jj][0], acc[jj][1], acc[jj][2], acc[jj][3]);
        *(float4*)(sb + (4 * ty + jj) * C_ + 4 * tx) = r;
    }
}

// ---------------- fused attention ----------------
// 4 warps, q-tile 64, k-tile 64, double-buffered cp.async staging, 2 CTAs/SM.
// smem floats: sK0 [0,4608) sK1 [4608,9216) sV0 [9216,13824) sV1 [13824,18432)
#define KV_STR 72           // ≡8 (mod 32): conflict-free (t4-row, g-col) B-frag loads
#define P_STR  68           // ≡4 (mod 32): conflict-free GEMM2 A-frag loads
#define SK0 0
#define SK1 4608
#define SV0 9216
#define SV1 13824
#define SMEM_BYTES (18432 * 4)

__global__ __launch_bounds__(128) void attn_kernel(const float* __restrict__ x,
                                                   float* __restrict__ out) {
    extern __shared__ float sm[];
    const uint32_t smb = (uint32_t)__cvta_generic_to_shared(sm);

    const int tid = threadIdx.x, w = tid >> 5, lane = tid & 31;
    const int g = lane >> 2, t4 = lane & 3;
    const int b = blockIdx.y, qb = blockIdx.x * 64;
    const float* xb = x + (size_t)b * C_ * N_;
    const float* vbg = g_support + (size_t)b * N_ * C_;

    const int stg_row = tid >> 4;           // 0..63 (4 rows... 128thr/16 = 8 rows? no: tid>>4 = 0..7)
    // staging: 1024 chunks of 16B per tile-buffer; idx = tid + k*128
    // row = idx>>4 (0..63), c16 = (idx&15)*4

    // ---- prologue: stage Q into sK1 region, tile 0 into buf0 ----
#pragma unroll
    for (int k = 0; k < 8; k++) {
        int idx = tid + k * 128;
        int row = idx >> 4, c16 = (idx & 15) * 4;
        cpa16(smb + (SK1 + row * KV_STR + c16) * 4, xb + (size_t)row * N_ + qb + c16);
    }
    CP_COMMIT();
#pragma unroll
    for (int k = 0; k < 8; k++) {
        int idx = tid + k * 128;
        int row = idx >> 4, c16 = (idx & 15) * 4;
        cpa16(smb + (SK0 + row * KV_STR + c16) * 4, xb + (size_t)row * N_ + 0 + c16);
        cpa16(smb + (SV0 + row * KV_STR + c16) * 4, vbg + (size_t)row * C_ + c16);
    }
    CP_COMMIT();
    CP_WAIT(1);            // Q staged (tile0 may still be in flight)
    __syncthreads();

    // ---- Q fragments (hi/lo) to registers, reused all iterations ----
    uint32_t qah[8][4], qal[8][4];
    {
        const float* qst = sm + SK1;
#pragma unroll
        for (int kc = 0; kc < 8; kc++) {
            const float* r0 = qst + (kc * 8 + t4) * KV_STR + 16 * w + g;
            const float* r1 = qst + (kc * 8 + t4 + 4) * KV_STR + 16 * w + g;
            float v[4] = {r0[0], r0[8], r1[0], r1[8]};
#pragma unroll
            for (int e = 0; e < 4; e++) {
                uint32_t h = f2tf32(v[e]);
                qah[kc][e] = h;
                qal[kc][e] = f2tf32(v[e] - __uint_as_float(h));
            }
        }
    }

    const float L2E = 1.4426950408889634f;
    const float R2 = g_R2[b];
    const float mA = sqrtf(g_norms2[b * N_ + qb + 16 * w + g] * R2) * L2E;
    const float mB = sqrtf(g_norms2[b * N_ + qb + 16 * w + g + 8] * R2) * L2E;

    float ls0 = 0.f, ls1 = 0.f;
    float oacc[8][4] = {};

    for (int i = 0; i < 64; i++) {
        const int buf = i & 1;
        float* skb = sm + (buf ? SK1 : SK0);
        float* svb = sm + (buf ? SV1 : SV0);

        CP_WAIT(0);        // tile i landed
        __syncthreads();   // all warps see it; all warps done with prev GEMM2

        if (i < 63) {      // prefetch tile i+1 into other buffer
            const int kt2 = (i + 1) * 64;
            const uint32_t ko = (buf ? SK0 : SK1), vo = (buf ? SV0 : SV1);
#pragma unroll
            for (int k = 0; k < 8; k++) {
                int idx = tid + k * 128;
                int row = idx >> 4, c16 = (idx & 15) * 4;
                cpa16(smb + (ko + row * KV_STR + c16) * 4, xb + (size_t)row * N_ + kt2 + c16);
                cpa16(smb + (vo + row * KV_STR + c16) * 4, vbg + (size_t)(kt2 + row) * C_ + c16);
            }
            CP_COMMIT();
        }

        // ---- GEMM1: S = Qh·Kh + Ql·Kh + Qh·Kl (tf32x3), K hi/lo split on the fly ----
        float sacc[8][4] = {};
#pragma unroll
        for (int kc = 0; kc < 8; kc++) {
            const float* r0 = skb + (kc * 8 + t4) * KV_STR;
            const float* r1 = skb + (kc * 8 + t4 + 4) * KV_STR;
#pragma unroll
            for (int nc = 0; nc < 8; nc++) {
                float v0 = r0[nc * 8 + g], v1 = r1[nc * 8 + g];
                uint32_t bh[2], bl[2];
                bh[0] = f2tf32(v0);
                bh[1] = f2tf32(v1);
                bl[0] = f2tf32(v0 - __uint_as_float(bh[0]));
                bl[1] = f2tf32(v1 - __uint_as_float(bh[1]));
                mma_tf32(sacc[nc], qah[kc], bh);
                mma_tf32(sacc[nc], qal[kc], bh);
                mma_tf32(sacc[nc], qah[kc], bl);
            }
        }
        __syncthreads();   // all warps done reading K -> safe to overlay P

        // ---- P = exp2(S*log2e - m), row sums, stage P (tf32) over K buffer ----
        float* pb = skb;   // reinterpreted, stride P_STR
#pragma unroll
        for (int nc = 0; nc < 8; nc++) {
            float e0 = ex2f(fmaf(sacc[nc][0], L2E, -mA));
            float e1 = ex2f(fmaf(sacc[nc][1], L2E, -mA));
            float e2 = ex2f(fmaf(sacc[nc][2], L2E, -mB));
            float e3 = ex2f(fmaf(sacc[nc][3], L2E, -mB));
            ls0 += e0 + e1;
            ls1 += e2 + e3;
            float p0 = __uint_as_float(f2tf32(e0));
            float p1 = __uint_as_float(f2tf32(e1));
            float p2 = __uint_as_float(f2tf32(e2));
            float p3 = __uint_as_float(f2tf32(e3));
            *(float2*)(pb + (16 * w + g) * P_STR + nc * 8 + 2 * t4) = make_float2(p0, p1);
            *(float2*)(pb + (16 * w + g + 8) * P_STR + nc * 8 + 2 * t4) = make_float2(p2, p3);
        }
        __syncthreads();   // P visible

        // ---- GEMM2: O += P · V ----
#pragma unroll
        for (int kc = 0; kc < 8; kc++) {
            uint32_t ap[4];
            ap[0] = __float_as_uint(pb[(16 * w + g) * P_STR + kc * 8 + t4]);
            ap[1] = __float_as_uint(pb[(16 * w + g + 8) * P_STR + kc * 8 + t4]);
            ap[2] = __float_as_uint(pb[(16 * w + g) * P_STR + kc * 8 + t4 + 4]);
            ap[3] = __float_as_uint(pb[(16 * w + g + 8) * P_STR + kc * 8 + t4 + 4]);
            const float* v0r = svb + (kc * 8 + t4) * KV_STR;
            const float* v1r = svb + (kc * 8 + t4 + 4) * KV_STR;
#pragma unroll
            for (int nc = 0; nc < 8; nc++) {
                uint32_t bv[2];
                bv[0] = f2tf32(v0r[nc * 8 + g]);
                bv[1] = f2tf32(v1r[nc * 8 + g]);
                mma_tf32(oacc[nc], ap, bv);
            }
        }
        // no trailing sync: next iter's post-wait syncthreads orders buffer reuse
    }

    // ---- row sums across t4 lanes (rows are warp-exclusive) ----
    ls0 += __shfl_xor_sync(0xffffffffu, ls0, 1);
    ls0 += __shfl_xor_sync(0xffffffffu, ls0, 2);
    ls1 += __shfl_xor_sync(0xffffffffu, ls1, 1);
    ls1 += __shfl_xor_sync(0xffffffffu, ls1, 2);
    const float inv0 = 1.f / ls0, inv1 = 1.f / ls1;

    // ---- stage O[c][i] into sV0 (free), then coalesced write + residual ----
    float* ost = sm + SV0;
#pragma unroll
    for (int nc = 0; nc < 8; nc++) {
        int c0 = nc * 8 + 2 * t4;
        int i0 = 16 * w + g;
        ost[c0 * KV_STR + i0] = oacc[nc][0] * inv0;
        ost[(c0 + 1) * KV_STR + i0] = oacc[nc][1] * inv0;
        ost[c0 * KV_STR + i0 + 8] = oacc[nc][2] * inv1;
        ost[(c0 + 1) * KV_STR + i0 + 8] = oacc[nc][3] * inv1;
    }
    __syncthreads();
    float* ob = out + (size_t)b * C_ * N_;
#pragma unroll
    for (int k = 0; k < 8; k++) {
        int idx = tid + k * 128;
        int c = idx >> 4, f = (idx & 15) * 4;
        float4 o = *(float4*)(ost + c * KV_STR + f);
        float4 xr = *(const float4*)(xb + (size_t)c * N_ + qb + f);
        o.x += xr.x; o.y += xr.y; o.z += xr.z; o.w += xr.w;
        *(float4*)(ob + (size_t)c * N_ + qb + f) = o;
    }
}

extern "C" void kernel_launch(void* const* d_in, const int* in_sizes, int n_in,
                              void* d_out, int out_size) {
    const float* x = (const float*)d_in[0];   // [8, 64, 64, 64] fp32
    const float* w = (const float*)d_in[1];   // [64, 64] fp32
    float* out = (float*)d_out;

    init_kernel<<<1, 32>>>();
    norms_kernel<<<dim3(N_ / 256, B_), 256>>>(x);
    support_kernel<<<dim3(N_ / 64, B_), 256>>>(x, w);
    cudaFuncSetAttribute(attn_kernel, cudaFuncAttributeMaxDynamicSharedMemorySize, SMEM_BYTES);
    attn_kernel<<<dim3(N_ / 64, B_), 128, SMEM_BYTES>>>(x, out);
}

// round 6
// speedup vs baseline: 2.5593x; 2.5593x over previous
#include <cuda_runtime.h>
#include <cuda_fp16.h>
#include <math.h>
#include <stdint.h>

#define B_ 8
#define C_ 64
#define N_ 4096

__device__ __half g_xhT[B_ * N_ * C_];   // [b][n][c] hi half of x
__device__ __half g_xlT[B_ * N_ * C_];   // [b][n][c] lo half
__device__ __half g_vT[B_ * C_ * N_];    // support^T: [b][c][n] fp16

// ---------------- helpers ----------------
__device__ __forceinline__ float ex2f(float x) {
    float y;
    asm("ex2.approx.f32 %0, %1;" : "=f"(y) : "f"(x));
    return y;
}
// D(16x8,f32) += A(16x16,f16) * B(16x8,f16)
__device__ __forceinline__ void mma_f16(float* d, const uint32_t* a, uint32_t b0, uint32_t b1) {
    asm volatile(
        "mma.sync.aligned.m16n8k16.row.col.f32.f16.f16.f32 "
        "{%0,%1,%2,%3}, {%4,%5,%6,%7}, {%8,%9}, {%0,%1,%2,%3};"
        : "+f"(d[0]), "+f"(d[1]), "+f"(d[2]), "+f"(d[3])
        : "r"(a[0]), "r"(a[1]), "r"(a[2]), "r"(a[3]), "r"(b0), "r"(b1));
}
__device__ __forceinline__ void cpa16(uint32_t dst, const void* src) {
    asm volatile("cp.async.cg.shared.global [%0], [%1], 16;" :: "r"(dst), "l"(src));
}
#define CP_COMMIT() asm volatile("cp.async.commit_group;" ::: "memory")
#define CP_WAIT(n)  asm volatile("cp.async.wait_group %0;" :: "n"(n) : "memory")

// ---------------- prep kernels ----------------
// hi/lo fp16 split of x, transposed to [b][n][c]
__global__ __launch_bounds__(256) void split_kernel(const float* __restrict__ x) {
    __shared__ float tile[64 * 65];
    const int b = blockIdx.y, nb = blockIdx.x * 64;
    const int t = threadIdx.x;
    const float* xb = x + (size_t)b * C_ * N_;
    for (int idx = t; idx < 1024; idx += 256) {
        int c = idx >> 4, f = (idx & 15) * 4;
        float4 v = *(const float4*)(xb + (size_t)c * N_ + nb + f);
        tile[c * 65 + f + 0] = v.x;
        tile[c * 65 + f + 1] = v.y;
        tile[c * 65 + f + 2] = v.z;
        tile[c * 65 + f + 3] = v.w;
    }
    __syncthreads();
    __half* xh = g_xhT + ((size_t)b * N_ + nb) * C_;
    __half* xl = g_xlT + ((size_t)b * N_ + nb) * C_;
    for (int idx = t; idx < 2048; idx += 256) {
        int n = idx >> 5, w2 = idx & 31;
        float v0 = tile[(2 * w2) * 65 + n];
        float v1 = tile[(2 * w2 + 1) * 65 + n];
        __half h0 = __float2half_rn(v0), h1 = __float2half_rn(v1);
        __half l0 = __float2half_rn(v0 - __half2float(h0));
        __half l1 = __float2half_rn(v1 - __half2float(h1));
        *((__half2*)(xh + (size_t)n * C_) + w2) = __halves2half2(h0, h1);
        *((__half2*)(xl + (size_t)n * C_) + w2) = __halves2half2(l0, l1);
    }
}

// support^T[b, c, n] = sum_k x[b, k, n] * w[k, c], fp32 compute, fp16 store
__global__ __launch_bounds__(256) void support_kernel(const float* __restrict__ x,
                                                      const float* __restrict__ w) {
    __shared__ float ws[64 * 64];
    __shared__ float xs[64 * 64];
    const int b  = blockIdx.y;
    const int jb = blockIdx.x * 64;
    const int t  = threadIdx.x;
    const int tx = t & 15, ty = t >> 4;
    const float* xb = x + (size_t)b * C_ * N_;

    for (int idx = t; idx < 1024; idx += 256) {
        ((float4*)ws)[idx] = ((const float4*)w)[idx];
        int k = idx >> 4, f = idx & 15;
        ((float4*)xs)[idx] = *(const float4*)(xb + k * N_ + jb + 4 * f);
    }
    __syncthreads();

    float acc[4][4] = {};
#pragma unroll 8
    for (int k = 0; k < 64; k++) {
        float4 xv = *(float4*)(xs + k * 64 + 4 * ty);
        float4 wv = *(float4*)(ws + k * 64 + 4 * tx);
        float xa[4] = {xv.x, xv.y, xv.z, xv.w};
        float wa[4] = {wv.x, wv.y, wv.z, wv.w};
#pragma unroll
        for (int jj = 0; jj < 4; jj++)
#pragma unroll
            for (int cc = 0; cc < 4; cc++)
                acc[jj][cc] = fmaf(xa[jj], wa[cc], acc[jj][cc]);
    }
    __syncthreads();
    __half* sh = (__half*)xs;   // [c][j] f16 staging
#pragma unroll
    for (int jj = 0; jj < 4; jj++)
#pragma unroll
        for (int cc = 0; cc < 4; cc++)
            sh[(4 * tx + cc) * 64 + 4 * ty + jj] = __float2half_rn(acc[jj][cc]);
    __syncthreads();
    __half* vb = g_vT + (size_t)b * C_ * N_ + jb;
    for (int idx = t; idx < 2048; idx += 256) {
        int c = idx >> 5, w2 = idx & 31;
        *((__half2*)(vb + (size_t)c * N_) + w2) = ((__half2*)sh)[c * 32 + w2];
    }
}

// ---------------- fused attention ----------------
// q-tile 128, k-tile 128, 8 warps. KH/KL tiles [j][c] f16 (STRW words/row),
// V tile [c][j] f16 (VSTR words/row). Double buffered. P in registers.
// Per-warp online softmax (warps own disjoint j-halves; merged in epilogue).
#define STRW 36
#define VSTR 68
#define KH0 0
#define KH1 4608
#define KL0 9216
#define KL1 13824
#define V0  18432
#define V1  22784
#define LP  27136
#define MP  27264
#define SMEM_WORDS (27264 + 128)
#define SMEM_BYTES (SMEM_WORDS * 4)
// epilogue overlays: OPART over KH0+KH1 (128*68=8704 <= 9216),
//                    OT over KL0+KL1 (64*132=8448 <= 9216)
#define OPART 0
#define OPART_STR 68
#define OT 9216
#define OT_STR 132

__global__ __launch_bounds__(256, 1) void attn_kernel(const float* __restrict__ x,
                                                      float* __restrict__ out) {
    extern __shared__ float sm[];
    const uint32_t smb = (uint32_t)__cvta_generic_to_shared(sm);
    const int tid = threadIdx.x, w = tid >> 5, lane = tid & 31;
    const int g = lane >> 2, t4 = lane & 3;
    const int b = blockIdx.y, qb = blockIdx.x * 128;
    const int r0w = (w & 3) * 32;        // warp's 32 S-rows
    const int half = w >> 2;             // j-half: cols [0,64) or [64,128)
    const int cb = half * 64;

    const __half* xh = g_xhT + (size_t)b * N_ * C_;
    const __half* xl = g_xlT + (size_t)b * N_ * C_;
    const __half* vg = g_vT + (size_t)b * C_ * N_;
    const float* xb = x + (size_t)b * C_ * N_;

    // ---- prologue: Q(h,l) -> buf1 regions; tile0 -> buf0 ----
#pragma unroll
    for (int k = 0; k < 4; k++) {
        int idx = tid + k * 256;
        int row = idx >> 3, ch = idx & 7;
        cpa16(smb + (KH1 + row * STRW + ch * 4) * 4,
              (const char*)(xh + (size_t)(qb + row) * C_) + ch * 16);
        cpa16(smb + (KL1 + row * STRW + ch * 4) * 4,
              (const char*)(xl + (size_t)(qb + row) * C_) + ch * 16);
    }
    CP_COMMIT();
#pragma unroll
    for (int k = 0; k < 4; k++) {
        int idx = tid + k * 256;
        int row = idx >> 3, ch = idx & 7;
        cpa16(smb + (KH0 + row * STRW + ch * 4) * 4,
              (const char*)(xh + (size_t)row * C_) + ch * 16);
        cpa16(smb + (KL0 + row * STRW + ch * 4) * 4,
              (const char*)(xl + (size_t)row * C_) + ch * 16);
    }
#pragma unroll
    for (int k = 0; k < 4; k++) {
        int idx = tid + k * 256;
        int row = idx >> 4, ch = idx & 15;
        cpa16(smb + (V0 + row * VSTR + ch * 4) * 4,
              (const char*)(vg + (size_t)row * N_) + ch * 16);
    }
    CP_COMMIT();
    CP_WAIT(1);          // Q staged
    __syncthreads();

    // ---- Q fragments (hi/lo fp16x2) to registers ----
    uint32_t qah[2][4][4], qal[2][4][4];
#pragma unroll
    for (int mt = 0; mt < 2; mt++)
#pragma unroll
        for (int kc = 0; kc < 4; kc++) {
            int r = r0w + mt * 16 + g;
            qah[mt][kc][0] = *(const uint32_t*)(sm + KH1 + r * STRW + kc * 8 + t4);
            qah[mt][kc][1] = *(const uint32_t*)(sm + KH1 + (r + 8) * STRW + kc * 8 + t4);
            qah[mt][kc][2] = *(const uint32_t*)(sm + KH1 + r * STRW + kc * 8 + t4 + 4);
            qah[mt][kc][3] = *(const uint32_t*)(sm + KH1 + (r + 8) * STRW + kc * 8 + t4 + 4);
            qal[mt][kc][0] = *(const uint32_t*)(sm + KL1 + r * STRW + kc * 8 + t4);
            qal[mt][kc][1] = *(const uint32_t*)(sm + KL1 + (r + 8) * STRW + kc * 8 + t4);
            qal[mt][kc][2] = *(const uint32_t*)(sm + KL1 + r * STRW + kc * 8 + t4 + 4);
            qal[mt][kc][3] = *(const uint32_t*)(sm + KL1 + (r + 8) * STRW + kc * 8 + t4 + 4);
        }

    const float L2E = 1.4426950408889634f;
    float mrun[4] = {-1e30f, -1e30f, -1e30f, -1e30f};   // log2 units, per row
    float ls[4] = {0.f, 0.f, 0.f, 0.f};
    float oacc[2][8][4] = {};

    for (int i = 0; i < 32; i++) {
        const int buf = i & 1;
        const float* kh_t = sm + (buf ? KH1 : KH0);
        const float* kl_t = sm + (buf ? KL1 : KL0);
        const float* v_t  = sm + (buf ? V1 : V0);

        CP_WAIT(0);
        __syncthreads();   // tile i visible; prev iter's reads of other buf done

        if (i < 31) {
            const int kt2 = (i + 1) * 128;
            const uint32_t kho = buf ? KH0 : KH1, klo = buf ? KL0 : KL1, vo = buf ? V0 : V1;
#pragma unroll
            for (int k = 0; k < 4; k++) {
                int idx = tid + k * 256;
                int row = idx >> 3, ch = idx & 7;
                cpa16(smb + (kho + row * STRW + ch * 4) * 4,
                      (const char*)(xh + (size_t)(kt2 + row) * C_) + ch * 16);
                cpa16(smb + (klo + row * STRW + ch * 4) * 4,
                      (const char*)(xl + (size_t)(kt2 + row) * C_) + ch * 16);
            }
#pragma unroll
            for (int k = 0; k < 4; k++) {
                int idx = tid + k * 256;
                int row = idx >> 4, ch = idx & 15;
                cpa16(smb + (vo + row * VSTR + ch * 4) * 4,
                      (const char*)(vg + (size_t)row * N_ + kt2) + ch * 16);
            }
            CP_COMMIT();
        }

        // two j-groups of 32 cols: GEMM1 -> online softmax -> GEMM2 (P in regs)
#pragma unroll
        for (int ng = 0; ng < 2; ng++) {
            float sacc[2][4][4] = {};
#pragma unroll
            for (int kc = 0; kc < 4; kc++) {
#pragma unroll
                for (int n = 0; n < 4; n++) {
                    int j = cb + (ng * 4 + n) * 8 + g;
                    uint32_t bh0 = *(const uint32_t*)(kh_t + j * STRW + kc * 8 + t4);
                    uint32_t bh1 = *(const uint32_t*)(kh_t + j * STRW + kc * 8 + t4 + 4);
                    uint32_t bl0 = *(const uint32_t*)(kl_t + j * STRW + kc * 8 + t4);
                    uint32_t bl1 = *(const uint32_t*)(kl_t + j * STRW + kc * 8 + t4 + 4);
#pragma unroll
                    for (int mt = 0; mt < 2; mt++) {
                        mma_f16(sacc[mt][n], qah[mt][kc], bh0, bh1);
                        mma_f16(sacc[mt][n], qal[mt][kc], bh0, bh1);
                        mma_f16(sacc[mt][n], qah[mt][kc], bl0, bl1);
                    }
                }
            }

            // ---- online max update (per warp, per row) ----
            float tm[4];
#pragma unroll
            for (int k2 = 0; k2 < 4; k2++) {
                int mt = k2 >> 1, hi2 = (k2 & 1) * 2;
                float t0 = fmaxf(fmaxf(sacc[mt][0][hi2], sacc[mt][0][hi2 + 1]),
                                 fmaxf(sacc[mt][1][hi2], sacc[mt][1][hi2 + 1]));
                float t1 = fmaxf(fmaxf(sacc[mt][2][hi2], sacc[mt][2][hi2 + 1]),
                                 fmaxf(sacc[mt][3][hi2], sacc[mt][3][hi2 + 1]));
                tm[k2] = fmaxf(t0, t1);
            }
#pragma unroll
            for (int k2 = 0; k2 < 4; k2++) {
                tm[k2] = fmaxf(tm[k2], __shfl_xor_sync(0xffffffffu, tm[k2], 1));
                tm[k2] = fmaxf(tm[k2], __shfl_xor_sync(0xffffffffu, tm[k2], 2));
            }
            float corr[4];
            bool nochange = true;
#pragma unroll
            for (int k2 = 0; k2 < 4; k2++) {
                float mn = fmaxf(mrun[k2], tm[k2] * L2E);
                corr[k2] = ex2f(mrun[k2] - mn);
                nochange &= (mrun[k2] == mn);
                mrun[k2] = mn;
            }
            if (!__all_sync(0xffffffffu, nochange)) {
#pragma unroll
                for (int k2 = 0; k2 < 4; k2++) ls[k2] *= corr[k2];
#pragma unroll
                for (int mt = 0; mt < 2; mt++)
#pragma unroll
                    for (int n = 0; n < 8; n++) {
                        oacc[mt][n][0] *= corr[mt * 2];
                        oacc[mt][n][1] *= corr[mt * 2];
                        oacc[mt][n][2] *= corr[mt * 2 + 1];
                        oacc[mt][n][3] *= corr[mt * 2 + 1];
                    }
            }

            // ---- P = exp2(S*l2e - mrun), pack fp16x2 A-fragments ----
            uint32_t pk[2][4][2];
#pragma unroll
            for (int mt = 0; mt < 2; mt++)
#pragma unroll
                for (int n = 0; n < 4; n++) {
                    float e0 = ex2f(fmaf(sacc[mt][n][0], L2E, -mrun[mt * 2]));
                    float e1 = ex2f(fmaf(sacc[mt][n][1], L2E, -mrun[mt * 2]));
                    float e2 = ex2f(fmaf(sacc[mt][n][2], L2E, -mrun[mt * 2 + 1]));
                    float e3 = ex2f(fmaf(sacc[mt][n][3], L2E, -mrun[mt * 2 + 1]));
                    ls[mt * 2] += e0 + e1;
                    ls[mt * 2 + 1] += e2 + e3;
                    asm("cvt.rn.f16x2.f32 %0, %1, %2;" : "=r"(pk[mt][n][0]) : "f"(e1), "f"(e0));
                    asm("cvt.rn.f16x2.f32 %0, %1, %2;" : "=r"(pk[mt][n][1]) : "f"(e3), "f"(e2));
                }

            // ---- GEMM2: O += P · V over this group's 32 j's ----
#pragma unroll
            for (int kc2 = 0; kc2 < 2; kc2++) {
                uint32_t ap[2][4];
#pragma unroll
                for (int mt = 0; mt < 2; mt++) {
                    ap[mt][0] = pk[mt][kc2 * 2][0];
                    ap[mt][1] = pk[mt][kc2 * 2][1];
                    ap[mt][2] = pk[mt][kc2 * 2 + 1][0];
                    ap[mt][3] = pk[mt][kc2 * 2 + 1][1];
                }
                const int vw = (cb >> 1) + (ng * 2 + kc2) * 8;
#pragma unroll
                for (int n = 0; n < 8; n++) {
                    const float* vr = v_t + (n * 8 + g) * VSTR + vw;
                    uint32_t b0 = *(const uint32_t*)(vr + t4);
                    uint32_t b1 = *(const uint32_t*)(vr + t4 + 4);
#pragma unroll
                    for (int mt = 0; mt < 2; mt++)
                        mma_f16(oacc[mt][n], ap[mt], b0, b1);
                }
            }
        }
    }

    // ---- reduce l over t4 lanes (m already uniform across t4) ----
#pragma unroll
    for (int k2 = 0; k2 < 4; k2++) {
        ls[k2] += __shfl_xor_sync(0xffffffffu, ls[k2], 1);
        ls[k2] += __shfl_xor_sync(0xffffffffu, ls[k2], 2);
    }
    __syncthreads();
    // ---- epilogue: merge j-halves with scale alignment ----
    if (half == 1) {
#pragma unroll
        for (int mt = 0; mt < 2; mt++) {
            int r = r0w + mt * 16 + g;
#pragma unroll
            for (int n = 0; n < 8; n++) {
                int c = n * 8 + 2 * t4;
                sm[OPART + r * OPART_STR + c] = oacc[mt][n][0];
                sm[OPART + r * OPART_STR + c + 1] = oacc[mt][n][1];
                sm[OPART + (r + 8) * OPART_STR + c] = oacc[mt][n][2];
                sm[OPART + (r + 8) * OPART_STR + c + 1] = oacc[mt][n][3];
            }
            if (t4 == 0) {
                sm[LP + r] = ls[mt * 2];
                sm[LP + r + 8] = ls[mt * 2 + 1];
                sm[MP + r] = mrun[mt * 2];
                sm[MP + r + 8] = mrun[mt * 2 + 1];
            }
        }
    }
    __syncthreads();
    if (half == 0) {
#pragma unroll
        for (int mt = 0; mt < 2; mt++) {
#pragma unroll
            for (int hi2 = 0; hi2 < 2; hi2++) {
                int r = r0w + mt * 16 + g + hi2 * 8;
                float m0 = mrun[mt * 2 + hi2], m1 = sm[MP + r];
                float M = fmaxf(m0, m1);
                float s0 = ex2f(m0 - M), s1 = ex2f(m1 - M);
                float inv = 1.f / (ls[mt * 2 + hi2] * s0 + sm[LP + r] * s1);
                float is0 = inv * s0, is1 = inv * s1;
#pragma unroll
                for (int n = 0; n < 8; n++) {
                    int c = n * 8 + 2 * t4;
                    float o0 = oacc[mt][n][hi2 * 2] * is0 + sm[OPART + r * OPART_STR + c] * is1;
                    float o1 = oacc[mt][n][hi2 * 2 + 1] * is0 + sm[OPART + r * OPART_STR + c + 1] * is1;
                    sm[OT + c * OT_STR + r] = o0;
                    sm[OT + (c + 1) * OT_STR + r] = o1;
                }
            }
        }
    }
    __syncthreads();
    float* ob = out + (size_t)b * C_ * N_;
#pragma unroll
    for (int k2 = 0; k2 < 8; k2++) {
        int idx = tid + k2 * 256;
        int c = idx >> 5, f = (idx & 31) * 4;
        float4 o = *(float4*)(sm + OT + c * OT_STR + f);
        float4 xr = *(const float4*)(xb + (size_t)c * N_ + qb + f);
        o.x += xr.x; o.y += xr.y; o.z += xr.z; o.w += xr.w;
        *(float4*)(ob + (size_t)c * N_ + qb + f) = o;
    }
}

extern "C" void kernel_launch(void* const* d_in, const int* in_sizes, int n_in,
                              void* d_out, int out_size) {
    const float* x = (const float*)d_in[0];   // [8, 64, 64, 64] fp32
    const float* w = (const float*)d_in[1];   // [64, 64] fp32
    float* out = (float*)d_out;

    split_kernel<<<dim3(N_ / 64, B_), 256>>>(x);
    support_kernel<<<dim3(N_ / 64, B_), 256>>>(x, w);
    cudaFuncSetAttribute(attn_kernel, cudaFuncAttributeMaxDynamicSharedMemorySize, SMEM_BYTES);
    attn_kernel<<<dim3(N_ / 128, B_), 256, SMEM_BYTES>>>(x, out);
}

// round 7
// speedup vs baseline: 2.9795x; 1.1642x over previous
#include <cuda_runtime.h>
#include <cuda_fp16.h>
#include <math.h>
#include <stdint.h>

#define B_ 8
#define C_ 64
#define N_ 4096

__device__ __half g_xhT[B_ * N_ * C_];   // [b][n][c] hi half of x
__device__ __half g_xlT[B_ * N_ * C_];   // [b][n][c] lo half
__device__ __half g_vT[B_ * C_ * N_];    // support^T: [b][c][n] fp16

// ---------------- helpers ----------------
__device__ __forceinline__ float ex2f(float x) {
    float y;
    asm("ex2.approx.f32 %0, %1;" : "=f"(y) : "f"(x));
    return y;
}
__device__ __forceinline__ uint32_t h2exp2(uint32_t a) {
    uint32_t r;
    asm("ex2.approx.f16x2 %0, %1;" : "=r"(r) : "r"(a));
    return r;
}
__device__ __forceinline__ uint32_t pack_f16x2(float hi, float lo) {
    uint32_t r;
    asm("cvt.rn.f16x2.f32 %0, %1, %2;" : "=r"(r) : "f"(hi), "f"(lo));
    return r;
}
// D(16x8,f32) += A(16x16,f16) * B(16x8,f16)
__device__ __forceinline__ void mma_f16(float* d, const uint32_t* a, uint32_t b0, uint32_t b1) {
    asm volatile(
        "mma.sync.aligned.m16n8k16.row.col.f32.f16.f16.f32 "
        "{%0,%1,%2,%3}, {%4,%5,%6,%7}, {%8,%9}, {%0,%1,%2,%3};"
        : "+f"(d[0]), "+f"(d[1]), "+f"(d[2]), "+f"(d[3])
        : "r"(a[0]), "r"(a[1]), "r"(a[2]), "r"(a[3]), "r"(b0), "r"(b1));
}
__device__ __forceinline__ void cpa16(uint32_t dst, const void* src) {
    asm volatile("cp.async.cg.shared.global [%0], [%1], 16;" :: "r"(dst), "l"(src));
}
#define CP_COMMIT() asm volatile("cp.async.commit_group;" ::: "memory")
#define CP_WAIT(n)  asm volatile("cp.async.wait_group %0;" :: "n"(n) : "memory")

// ---------------- prep kernels ----------------
__global__ __launch_bounds__(256) void split_kernel(const float* __restrict__ x) {
    __shared__ float tile[64 * 65];
    const int b = blockIdx.y, nb = blockIdx.x * 64;
    const int t = threadIdx.x;
    const float* xb = x + (size_t)b * C_ * N_;
    for (int idx = t; idx < 1024; idx += 256) {
        int c = idx >> 4, f = (idx & 15) * 4;
        float4 v = *(const float4*)(xb + (size_t)c * N_ + nb + f);
        tile[c * 65 + f + 0] = v.x;
        tile[c * 65 + f + 1] = v.y;
        tile[c * 65 + f + 2] = v.z;
        tile[c * 65 + f + 3] = v.w;
    }
    __syncthreads();
    __half* xh = g_xhT + ((size_t)b * N_ + nb) * C_;
    __half* xl = g_xlT + ((size_t)b * N_ + nb) * C_;
    for (int idx = t; idx < 2048; idx += 256) {
        int n = idx >> 5, w2 = idx & 31;
        float v0 = tile[(2 * w2) * 65 + n];
        float v1 = tile[(2 * w2 + 1) * 65 + n];
        __half h0 = __float2half_rn(v0), h1 = __float2half_rn(v1);
        __half l0 = __float2half_rn(v0 - __half2float(h0));
        __half l1 = __float2half_rn(v1 - __half2float(h1));
        *((__half2*)(xh + (size_t)n * C_) + w2) = __halves2half2(h0, h1);
        *((__half2*)(xl + (size_t)n * C_) + w2) = __halves2half2(l0, l1);
    }
}

__global__ __launch_bounds__(256) void support_kernel(const float* __restrict__ x,
                                                      const float* __restrict__ w) {
    __shared__ float ws[64 * 64];
    __shared__ float xs[64 * 64];
    const int b  = blockIdx.y;
    const int jb = blockIdx.x * 64;
    const int t  = threadIdx.x;
    const int tx = t & 15, ty = t >> 4;
    const float* xb = x + (size_t)b * C_ * N_;

    for (int idx = t; idx < 1024; idx += 256) {
        ((float4*)ws)[idx] = ((const float4*)w)[idx];
        int k = idx >> 4, f = idx & 15;
        ((float4*)xs)[idx] = *(const float4*)(xb + k * N_ + jb + 4 * f);
    }
    __syncthreads();

    float acc[4][4] = {};
#pragma unroll 8
    for (int k = 0; k < 64; k++) {
        float4 xv = *(float4*)(xs + k * 64 + 4 * ty);
        float4 wv = *(float4*)(ws + k * 64 + 4 * tx);
        float xa[4] = {xv.x, xv.y, xv.z, xv.w};
        float wa[4] = {wv.x, wv.y, wv.z, wv.w};
#pragma unroll
        for (int jj = 0; jj < 4; jj++)
#pragma unroll
            for (int cc = 0; cc < 4; cc++)
                acc[jj][cc] = fmaf(xa[jj], wa[cc], acc[jj][cc]);
    }
    __syncthreads();
    __half* sh = (__half*)xs;
#pragma unroll
    for (int jj = 0; jj < 4; jj++)
#pragma unroll
        for (int cc = 0; cc < 4; cc++)
            sh[(4 * tx + cc) * 64 + 4 * ty + jj] = __float2half_rn(acc[jj][cc]);
    __syncthreads();
    __half* vb = g_vT + (size_t)b * C_ * N_ + jb;
    for (int idx = t; idx < 2048; idx += 256) {
        int c = idx >> 5, w2 = idx & 31;
        *((__half2*)(vb + (size_t)c * N_) + w2) = ((__half2*)sh)[c * 32 + w2];
    }
}

// ---------------- fused attention ----------------
// q-tile 128, k-tile 64, 4 warps (128 thr), 2 CTAs/SM -> single wave.
// Each warp: 32 q-rows x full 64 j per iter. l via constant-B tensor column.
#define STRW 36
#define KH0 0
#define KH1 2304
#define KL0 4608
#define KL1 6912
#define V0  9216
#define V1  11520
#define SMEM_WORDS 13824
#define SMEM_BYTES (SMEM_WORDS * 4)
#define OT 0
#define OT_STR 132   // 64*132 = 8448 <= 9216 (K region), V untouched

__global__ __launch_bounds__(128, 2) void attn_kernel(const float* __restrict__ x,
                                                      float* __restrict__ out) {
    extern __shared__ float sm[];
    const uint32_t smb = (uint32_t)__cvta_generic_to_shared(sm);
    const int tid = threadIdx.x, w = tid >> 5, lane = tid & 31;
    const int g = lane >> 2, t4 = lane & 3;
    const int b = blockIdx.y, qb = blockIdx.x * 128;
    const int r0w = w * 32;                 // warp's 32 q-rows

    const __half* xh = g_xhT + (size_t)b * N_ * C_;
    const __half* xl = g_xlT + (size_t)b * N_ * C_;
    const __half* vg = g_vT + (size_t)b * C_ * N_;
    const float* xb = x + (size_t)b * C_ * N_;

    // ---- prologue: stage Q(h,l) across KH0/KH1, KL0/KL1 ----
#pragma unroll
    for (int k = 0; k < 8; k++) {
        int idx = tid + k * 128;
        int row = idx >> 3, ch = idx & 7;
        uint32_t dh = (row < 64) ? (KH0 + row * STRW) : (KH1 + (row - 64) * STRW);
        uint32_t dl = (row < 64) ? (KL0 + row * STRW) : (KL1 + (row - 64) * STRW);
        cpa16(smb + (dh + ch * 4) * 4, (const char*)(xh + (size_t)(qb + row) * C_) + ch * 16);
        cpa16(smb + (dl + ch * 4) * 4, (const char*)(xl + (size_t)(qb + row) * C_) + ch * 16);
    }
    CP_COMMIT();
    CP_WAIT(0);
    __syncthreads();

    // ---- Q fragments (hi/lo fp16x2) to registers ----
    uint32_t qah[2][4][4], qal[2][4][4];
    {
        const uint32_t qhb = (w < 2) ? KH0 : KH1;
        const uint32_t qlb = (w < 2) ? KL0 : KL1;
        const int rb = (w & 1) * 32;
#pragma unroll
        for (int mt = 0; mt < 2; mt++)
#pragma unroll
            for (int kc = 0; kc < 4; kc++) {
                int r = rb + mt * 16 + g;
                qah[mt][kc][0] = *(const uint32_t*)(sm + qhb + r * STRW + kc * 8 + t4);
                qah[mt][kc][1] = *(const uint32_t*)(sm + qhb + (r + 8) * STRW + kc * 8 + t4);
                qah[mt][kc][2] = *(const uint32_t*)(sm + qhb + r * STRW + kc * 8 + t4 + 4);
                qah[mt][kc][3] = *(const uint32_t*)(sm + qhb + (r + 8) * STRW + kc * 8 + t4 + 4);
                qal[mt][kc][0] = *(const uint32_t*)(sm + qlb + r * STRW + kc * 8 + t4);
                qal[mt][kc][1] = *(const uint32_t*)(sm + qlb + (r + 8) * STRW + kc * 8 + t4);
                qal[mt][kc][2] = *(const uint32_t*)(sm + qlb + r * STRW + kc * 8 + t4 + 4);
                qal[mt][kc][3] = *(const uint32_t*)(sm + qlb + (r + 8) * STRW + kc * 8 + t4 + 4);
            }
    }
    __syncthreads();   // frags read -> safe to overwrite K buffers

    // ---- stage tile 0 ----
#pragma unroll
    for (int k = 0; k < 4; k++) {
        int idx = tid + k * 128;
        int row = idx >> 3, ch = idx & 7;
        cpa16(smb + (KH0 + row * STRW + ch * 4) * 4, (const char*)(xh + (size_t)row * C_) + ch * 16);
        cpa16(smb + (KL0 + row * STRW + ch * 4) * 4, (const char*)(xl + (size_t)row * C_) + ch * 16);
        cpa16(smb + (V0 + row * STRW + ch * 4) * 4, (const char*)(vg + (size_t)row * N_) + ch * 16);
    }
    CP_COMMIT();

    const float L2E = 1.4426950408889634f;
    const uint32_t onesb = (g == 0) ? 0x3C003C00u : 0u;   // constant B-frag for l column
    float mrun[4] = {-1e30f, -1e30f, -1e30f, -1e30f};     // log2 units
    float oacc[2][9][4] = {};                             // [..][8] = l accumulator

    for (int i = 0; i < 64; i++) {
        const int buf = i & 1;
        const float* kh_t = sm + (buf ? KH1 : KH0);
        const float* kl_t = sm + (buf ? KL1 : KL0);
        const float* v_t  = sm + (buf ? V1 : V0);

        CP_WAIT(0);
        __syncthreads();   // tile i visible; prev iter's reads of other buf done

        if (i < 63) {
            const int kt2 = (i + 1) * 64;
            const uint32_t kho = buf ? KH0 : KH1, klo = buf ? KL0 : KL1, vo = buf ? V0 : V1;
#pragma unroll
            for (int k = 0; k < 4; k++) {
                int idx = tid + k * 128;
                int row = idx >> 3, ch = idx & 7;
                cpa16(smb + (kho + row * STRW + ch * 4) * 4,
                      (const char*)(xh + (size_t)(kt2 + row) * C_) + ch * 16);
                cpa16(smb + (klo + row * STRW + ch * 4) * 4,
                      (const char*)(xl + (size_t)(kt2 + row) * C_) + ch * 16);
                cpa16(smb + (vo + row * STRW + ch * 4) * 4,
                      (const char*)(vg + (size_t)row * N_ + kt2) + ch * 16);
            }
            CP_COMMIT();
        }

        // ---- GEMM1: S(32x64) = Qh·Kh + Ql·Kh + Qh·Kl ----
        float sacc[2][8][4] = {};
#pragma unroll
        for (int kc = 0; kc < 4; kc++) {
#pragma unroll
            for (int n = 0; n < 8; n++) {
                int j = n * 8 + g;
                uint32_t bh0 = *(const uint32_t*)(kh_t + j * STRW + kc * 8 + t4);
                uint32_t bh1 = *(const uint32_t*)(kh_t + j * STRW + kc * 8 + t4 + 4);
                uint32_t bl0 = *(const uint32_t*)(kl_t + j * STRW + kc * 8 + t4);
                uint32_t bl1 = *(const uint32_t*)(kl_t + j * STRW + kc * 8 + t4 + 4);
#pragma unroll
                for (int mt = 0; mt < 2; mt++) {
                    mma_f16(sacc[mt][n], qah[mt][kc], bh0, bh1);
                    mma_f16(sacc[mt][n], qal[mt][kc], bh0, bh1);
                    mma_f16(sacc[mt][n], qah[mt][kc], bl0, bl1);
                }
            }
        }

        // ---- online max (per row-group), conditional O/l rescale ----
        float tm[4];
#pragma unroll
        for (int k2 = 0; k2 < 4; k2++) {
            int mt = k2 >> 1, hi2 = (k2 & 1) * 2;
            float t0 = fmaxf(fmaxf(sacc[mt][0][hi2], sacc[mt][0][hi2 + 1]),
                             fmaxf(sacc[mt][1][hi2], sacc[mt][1][hi2 + 1]));
            float t1 = fmaxf(fmaxf(sacc[mt][2][hi2], sacc[mt][2][hi2 + 1]),
                             fmaxf(sacc[mt][3][hi2], sacc[mt][3][hi2 + 1]));
            float t2 = fmaxf(fmaxf(sacc[mt][4][hi2], sacc[mt][4][hi2 + 1]),
                             fmaxf(sacc[mt][5][hi2], sacc[mt][5][hi2 + 1]));
            float t3 = fmaxf(fmaxf(sacc[mt][6][hi2], sacc[mt][6][hi2 + 1]),
                             fmaxf(sacc[mt][7][hi2], sacc[mt][7][hi2 + 1]));
            tm[k2] = fmaxf(fmaxf(t0, t1), fmaxf(t2, t3));
        }
#pragma unroll
        for (int k2 = 0; k2 < 4; k2++) {
            tm[k2] = fmaxf(tm[k2], __shfl_xor_sync(0xffffffffu, tm[k2], 1));
            tm[k2] = fmaxf(tm[k2], __shfl_xor_sync(0xffffffffu, tm[k2], 2));
        }
        float corr[4];
        bool nochange = true;
#pragma unroll
        for (int k2 = 0; k2 < 4; k2++) {
            float mn = fmaxf(mrun[k2], tm[k2] * L2E);
            corr[k2] = ex2f(mrun[k2] - mn);
            nochange &= (mrun[k2] == mn);
            mrun[k2] = mn;
        }
        if (!__all_sync(0xffffffffu, nochange)) {
#pragma unroll
            for (int mt = 0; mt < 2; mt++)
#pragma unroll
                for (int n = 0; n < 9; n++) {
                    oacc[mt][n][0] *= corr[mt * 2];
                    oacc[mt][n][1] *= corr[mt * 2];
                    oacc[mt][n][2] *= corr[mt * 2 + 1];
                    oacc[mt][n][3] *= corr[mt * 2 + 1];
                }
        }

        // ---- P = exp2(S*l2e - m), computed in f16x2 (pack args, then ex2) ----
        uint32_t pk[2][8][2];
#pragma unroll
        for (int mt = 0; mt < 2; mt++)
#pragma unroll
            for (int n = 0; n < 8; n++) {
                float a0 = fmaf(sacc[mt][n][0], L2E, -mrun[mt * 2]);
                float a1 = fmaf(sacc[mt][n][1], L2E, -mrun[mt * 2]);
                float a2 = fmaf(sacc[mt][n][2], L2E, -mrun[mt * 2 + 1]);
                float a3 = fmaf(sacc[mt][n][3], L2E, -mrun[mt * 2 + 1]);
                pk[mt][n][0] = h2exp2(pack_f16x2(a1, a0));
                pk[mt][n][1] = h2exp2(pack_f16x2(a3, a2));
            }

        // ---- GEMM2: O(32x64) += P · V ; l += P · 1 (constant B-frag) ----
#pragma unroll
        for (int kc2 = 0; kc2 < 4; kc2++) {
            uint32_t ap[2][4];
#pragma unroll
            for (int mt = 0; mt < 2; mt++) {
                ap[mt][0] = pk[mt][kc2 * 2][0];
                ap[mt][1] = pk[mt][kc2 * 2][1];
                ap[mt][2] = pk[mt][kc2 * 2 + 1][0];
                ap[mt][3] = pk[mt][kc2 * 2 + 1][1];
            }
#pragma unroll
            for (int n = 0; n < 8; n++) {
                const float* vr = v_t + (n * 8 + g) * STRW + kc2 * 8;
                uint32_t b0 = *(const uint32_t*)(vr + t4);
                uint32_t b1 = *(const uint32_t*)(vr + t4 + 4);
#pragma unroll
                for (int mt = 0; mt < 2; mt++)
                    mma_f16(oacc[mt][n], ap[mt], b0, b1);
            }
#pragma unroll
            for (int mt = 0; mt < 2; mt++)
                mma_f16(oacc[mt][8], ap[mt], onesb, onesb);
        }
    }

    // ---- epilogue: per-warp exact l; normalize; transpose; residual; store ----
    __syncthreads();   // all GEMM2 reads done -> safe to overlay OT
#pragma unroll
    for (int mt = 0; mt < 2; mt++) {
        float lv0 = __shfl_sync(0xffffffffu, oacc[mt][8][0], lane & ~3);
        float lv1 = __shfl_sync(0xffffffffu, oacc[mt][8][2], lane & ~3);
        float inv0 = 1.f / lv0, inv1 = 1.f / lv1;
        int r = r0w + mt * 16 + g;
#pragma unroll
        for (int n = 0; n < 8; n++) {
            int c = n * 8 + 2 * t4;
            sm[OT + c * OT_STR + r] = oacc[mt][n][0] * inv0;
            sm[OT + (c + 1) * OT_STR + r] = oacc[mt][n][1] * inv0;
            sm[OT + c * OT_STR + r + 8] = oacc[mt][n][2] * inv1;
            sm[OT + (c + 1) * OT_STR + r + 8] = oacc[mt][n][3] * inv1;
        }
    }
    __syncthreads();
    float* ob = out + (size_t)b * C_ * N_;
#pragma unroll
    for (int k2 = 0; k2 < 16; k2++) {
        int idx = tid + k2 * 128;
        int c = idx >> 5, f = (idx & 31) * 4;
        float4 o = *(float4*)(sm + OT + c * OT_STR + f);
        float4 xr = *(const float4*)(xb + (size_t)c * N_ + qb + f);
        o.x += xr.x; o.y += xr.y; o.z += xr.z; o.w += xr.w;
        *(float4*)(ob + (size_t)c * N_ + qb + f) = o;
    }
}

extern "C" void kernel_launch(void* const* d_in, const int* in_sizes, int n_in,
                              void* d_out, int out_size) {
    const float* x = (const float*)d_in[0];   // [8, 64, 64, 64] fp32
    const float* w = (const float*)d_in[1];   // [64, 64] fp32
    float* out = (float*)d_out;

    split_kernel<<<dim3(N_ / 64, B_), 256>>>(x);
    support_kernel<<<dim3(N_ / 64, B_), 256>>>(x, w);
    cudaFuncSetAttribute(attn_kernel, cudaFuncAttributeMaxDynamicSharedMemorySize, SMEM_BYTES);
    attn_kernel<<<dim3(N_ / 128, B_), 128, SMEM_BYTES>>>(x, out);
}